// round 4
// baseline (speedup 1.0000x reference)
#include <cuda_runtime.h>
#include <stdint.h>

// Problem constants (fixed shapes from reference):
//   updates: (32, 64, 64, 128) fp32  -> 16,777,216 elems
//   mask:    same shape, int32 in [0, 2,097,152)
//   output:  (32, 128, 128, 128) fp32 -> 67,108,864 elems (256 MB)
#define N_IN        16777216     // total update elements
#define PER_B_IN    524288       // 64*64*128 per-batch input elements
#define FLAT_OUT    2097152      // 128*128*128 per-batch output slots
#define N_OUT       67108864     // 32 * FLAT_OUT
#define LOG2_PERB_V 17           // PER_B_IN/4 = 131072 = 2^17 (vec4 elements per batch)

// ---------------------------------------------------------------------------
// Kernel 1: zero the whole output (it is 0xAA-poisoned by the harness).
// float4 stores -> STG.128, pure DRAM-write bound (~256 MB).
// ---------------------------------------------------------------------------
__global__ void __launch_bounds__(256) zero_out_kernel(float4* __restrict__ out) {
    const int n4 = N_OUT / 4;  // 16,777,216 float4s
    int i = blockIdx.x * blockDim.x + threadIdx.x;
    const float4 z = make_float4(0.f, 0.f, 0.f, 0.f);
    // grid exactly covers n4; no stride loop needed, but guard anyway
    if (i < n4) out[i] = z;
}

// ---------------------------------------------------------------------------
// Kernel 2: scatter-add. Each thread handles 4 consecutive elements
// (one float4 of updates + one int4 of mask). All 4 belong to the same
// batch because PER_B_IN is divisible by 4. atomicAdd with unused return
// -> RED.E.ADD.F32 (no round trip). Blocks are naturally ordered by batch,
// which keeps each 8 MB per-batch output window hot in L2 while its
// scatters are in flight.
// ---------------------------------------------------------------------------
__global__ void __launch_bounds__(256) scatter_add_kernel(
    const float4* __restrict__ upd,
    const int4*   __restrict__ mask,
    float*        __restrict__ out)
{
    const int n4 = N_IN / 4;  // 4,194,304 vec elements
    int i = blockIdx.x * blockDim.x + threadIdx.x;
    if (i >= n4) return;

    float4 u = upd[i];
    int4   m = mask[i];

    int b = i >> LOG2_PERB_V;                 // batch index
    float* obase = out + (size_t)b * FLAT_OUT;

    atomicAdd(obase + m.x, u.x);
    atomicAdd(obase + m.y, u.y);
    atomicAdd(obase + m.z, u.z);
    atomicAdd(obase + m.w, u.w);
}

extern "C" void kernel_launch(void* const* d_in, const int* in_sizes, int n_in,
                              void* d_out, int out_size)
{
    const float4* upd  = (const float4*)d_in[0];   // updates fp32
    const int4*   mask = (const int4*)  d_in[1];   // mask int32
    float*        out  = (float*)d_out;

    // Zero pass: 16,777,216 float4s / 256 threads = 65,536 blocks
    zero_out_kernel<<<N_OUT / 4 / 256, 256>>>((float4*)out);

    // Scatter pass: 4,194,304 vec elements / 256 threads = 16,384 blocks
    scatter_add_kernel<<<N_IN / 4 / 256, 256>>>(upd, mask, out);
}

// round 5
// speedup vs baseline: 1.1164x; 1.1164x over previous
#include <cuda_runtime.h>
#include <stdint.h>

// Shapes (fixed):
//   updates: (32, 64, 64, 128) fp32  -> 16,777,216 elems
//   mask:    same shape, int32 in [0, 2,097,152)
//   output:  (32, 128, 128, 128) fp32 -> 67,108,864 elems (256 MB)
#define N_IN        16777216
#define FLAT_OUT    2097152      // per-batch output slots (8 MB)
#define N_OUT       67108864
#define NBATCH      32
#define BLKS_PER_B  512          // blocks per batch
#define DELAY       2            // scatter batch = zero batch - DELAY

// Per-batch zero-completion counters (reset every launch by init kernel).
__device__ unsigned int g_ctr[NBATCH];

__global__ void init_ctr_kernel() {
    if (threadIdx.x < NBATCH) g_ctr[threadIdx.x] = 0u;
}

// ---------------------------------------------------------------------------
// Fused zero + scatter pipeline.
//   Block bid:
//     zb = bid >> 9 : zeroes a 16 KB chunk of batch zb's output (if zb < 32)
//     sb = zb - 2   : scatters input chunk of batch sb (if 0 <= sb < 32),
//                     after all 512 zero-blocks of batch sb have arrived.
//   Because batch sb's zero blocks have strictly lower bids (>=1024 earlier)
//   and CTAs dispatch in bid order with backfill, the spin cannot deadlock.
//   By the time batch sb is scattered its 8 MB zeroed region is L2-resident,
//   so the atomics RMW in L2 instead of forcing a DRAM read + writeback.
// ---------------------------------------------------------------------------
__global__ void __launch_bounds__(256) fused_unpool_kernel(
    const float4* __restrict__ upd,
    const int4*   __restrict__ mask,
    float*        __restrict__ out)
{
    const int bid = blockIdx.x;
    const int t   = threadIdx.x;
    const int zb  = bid >> 9;          // batch to zero
    const int c   = bid & (BLKS_PER_B - 1);
    const int sb  = zb - DELAY;        // batch to scatter

    const bool do_scatter = (sb >= 0) && (sb < NBATCH);

    // Prefetch scatter inputs early — independent of the zero phase, so the
    // LDG.128s are in flight while we zero and (maybe) spin.
    float4 u = make_float4(0.f, 0.f, 0.f, 0.f);
    int4   m = make_int4(0, 0, 0, 0);
    if (do_scatter) {
        // vec4 index: sb*131072 + c*256 + t
        const int vi = (sb << 17) + (c << 8) + t;
        u = upd[vi];
        m = mask[vi];
    }

    // ---- zero phase: 16 KB = 1024 float4, 4 per thread, coalesced ----
    if (zb < NBATCH) {
        float4* zp = reinterpret_cast<float4*>(out + (size_t)zb * FLAT_OUT)
                     + (c << 10);
        const float4 z = make_float4(0.f, 0.f, 0.f, 0.f);
        #pragma unroll
        for (int k = 0; k < 4; k++) zp[t + (k << 8)] = z;

        __threadfence();               // make zeros device-visible
        __syncthreads();               // all threads fenced before arrive
        if (t == 0) atomicAdd(&g_ctr[zb], 1u);
    }

    if (!do_scatter) return;

    // ---- wait until batch sb is fully zeroed ----
    if (t == 0) {
        while (atomicAdd(&g_ctr[sb], 0u) < BLKS_PER_B) __nanosleep(64);
    }
    __syncthreads();
    __threadfence();                   // acquire-side ordering (cheap, safe)

    // ---- scatter phase: 4 REDs per thread into L2-warm region ----
    float* ob = out + (size_t)sb * FLAT_OUT;
    atomicAdd(ob + m.x, u.x);
    atomicAdd(ob + m.y, u.y);
    atomicAdd(ob + m.z, u.z);
    atomicAdd(ob + m.w, u.w);
}

extern "C" void kernel_launch(void* const* d_in, const int* in_sizes, int n_in,
                              void* d_out, int out_size)
{
    const float4* upd  = (const float4*)d_in[0];
    const int4*   mask = (const int4*)  d_in[1];
    float*        out  = (float*)d_out;

    init_ctr_kernel<<<1, 32>>>();

    // 32 zero-batches * 512 blocks + DELAY*512 tail blocks that only scatter
    // the last DELAY batches.
    const int grid = (NBATCH + DELAY) * BLKS_PER_B;   // 17408
    fused_unpool_kernel<<<grid, 256>>>(upd, mask, out);
}

// round 6
// speedup vs baseline: 1.1172x; 1.0007x over previous
#include <cuda_runtime.h>
#include <stdint.h>

// Shapes (fixed):
//   updates: (32, 64, 64, 128) fp32  -> 16,777,216 elems
//   mask:    same shape, int32 in [0, 2,097,152)
//   output:  (32, 128, 128, 128) fp32 -> 67,108,864 elems (256 MB)
#define N_IN        16777216
#define FLAT_OUT    2097152      // per-batch output slots (8 MB)
#define N_OUT       67108864
#define NBATCH      32
#define BLKS_PER_B  512          // blocks per batch
#define DELAY       3            // scatter batch = zero batch - DELAY

// Per-batch zero-completion counters (reset every launch by init kernel).
__device__ unsigned int g_ctr[NBATCH];

__global__ void init_ctr_kernel() {
    if (threadIdx.x < NBATCH) g_ctr[threadIdx.x] = 0u;
}

__device__ __forceinline__ unsigned int ld_acquire_gpu(const unsigned int* p) {
    unsigned int v;
    asm volatile("ld.acquire.gpu.global.u32 %0, [%1];" : "=r"(v) : "l"(p) : "memory");
    return v;
}

__device__ __forceinline__ void red_release_gpu_add(unsigned int* p, unsigned int v) {
    asm volatile("red.release.gpu.global.add.u32 [%0], %1;" :: "l"(p), "r"(v) : "memory");
}

// ---------------------------------------------------------------------------
// Fused zero + scatter pipeline.
//   Block bid:
//     zb = bid >> 9 : zeroes a 16 KB chunk of batch zb's output (if zb < 32)
//     sb = zb - 3   : scatters input chunk of batch sb (if 0 <= sb < 32),
//                     after all 512 zero-blocks of batch sb have published.
//   Producers of batch sb have strictly lower block IDs (>= 3*512 earlier),
//   and CTAs dispatch in bid order with backfill -> the spin cannot deadlock.
//   Synchronization: BAR.SYNC drains the zero STGs (HW-native), then ONE
//   elected thread publishes with red.release.gpu; consumers poll with
//   ld.acquire.gpu (plain L2 read, no per-address ATOMG serialization).
// ---------------------------------------------------------------------------
__global__ void __launch_bounds__(256) fused_unpool_kernel(
    const float4* __restrict__ upd,
    const int4*   __restrict__ mask,
    float*        __restrict__ out)
{
    const int bid = blockIdx.x;
    const int t   = threadIdx.x;
    const int zb  = bid >> 9;              // batch to zero
    const int c   = bid & (BLKS_PER_B - 1);
    const int sb  = zb - DELAY;            // batch to scatter

    const bool do_scatter = (sb >= 0) && (sb < NBATCH);

    // Prefetch scatter inputs with streaming (evict-first) hint so the
    // 128 MB one-shot input read does not evict the zeroed output lines
    // we need resident in L2 for the atomics.
    float4 u = make_float4(0.f, 0.f, 0.f, 0.f);
    int4   m = make_int4(0, 0, 0, 0);
    if (do_scatter) {
        const int vi = (sb << 17) + (c << 8) + t;  // vec4 index within batch
        u = __ldcs(&upd[vi]);
        m = __ldcs(&mask[vi]);
    }

    // ---- zero phase: 16 KB = 1024 float4, 4 per thread, coalesced ----
    if (zb < NBATCH) {
        float4* zp = reinterpret_cast<float4*>(out + (size_t)zb * FLAT_OUT)
                     + (c << 10);
        const float4 z = make_float4(0.f, 0.f, 0.f, 0.f);
        #pragma unroll
        for (int k = 0; k < 4; k++) zp[t + (k << 8)] = z;

        __syncthreads();               // BAR.SYNC drains pending STS (HW)
        if (t == 0) red_release_gpu_add(&g_ctr[zb], 1u);  // publish
    }

    if (!do_scatter) return;

    // ---- wait until batch sb is fully zeroed (acquire-poll, 1 thread) ----
    if (t == 0) {
        if (ld_acquire_gpu(&g_ctr[sb]) < BLKS_PER_B) {
            do { __nanosleep(128); } while (ld_acquire_gpu(&g_ctr[sb]) < BLKS_PER_B);
        }
    }
    __syncthreads();   // broadcast the acquire to the whole CTA

    // ---- scatter phase: 4 REDs per thread into the L2-warm region ----
    float* ob = out + (size_t)sb * FLAT_OUT;
    atomicAdd(ob + m.x, u.x);
    atomicAdd(ob + m.y, u.y);
    atomicAdd(ob + m.z, u.z);
    atomicAdd(ob + m.w, u.w);
}

extern "C" void kernel_launch(void* const* d_in, const int* in_sizes, int n_in,
                              void* d_out, int out_size)
{
    const float4* upd  = (const float4*)d_in[0];
    const int4*   mask = (const int4*)  d_in[1];
    float*        out  = (float*)d_out;

    init_ctr_kernel<<<1, 32>>>();

    // 32 zero-batches * 512 blocks + DELAY*512 tail blocks (scatter-only).
    const int grid = (NBATCH + DELAY) * BLKS_PER_B;   // 17920
    fused_unpool_kernel<<<grid, 256>>>(upd, mask, out);
}

// round 7
// speedup vs baseline: 1.2549x; 1.1233x over previous
#include <cuda_runtime.h>
#include <stdint.h>

// Shapes (fixed):
//   updates: (32, 64, 64, 128) fp32  -> 16,777,216 elems
//   mask:    same shape, int32 in [0, 2,097,152)
//   output:  (32, 128, 128, 128) fp32 -> 67,108,864 elems (256 MB)
#define N_IN        16777216
#define FLAT_OUT    2097152      // per-batch output slots (8 MB)
#define N_OUT       67108864
#define NBATCH      32
#define BLKS_PER_B  512          // blocks per batch
#define DELAY       2            // scatter batch = zero batch - DELAY

// Per-batch zero-completion counters (reset every launch by init kernel).
__device__ unsigned int g_ctr[NBATCH];

__global__ void init_ctr_kernel() {
    if (threadIdx.x < NBATCH) g_ctr[threadIdx.x] = 0u;
}

__device__ __forceinline__ unsigned int ld_acquire_gpu(const unsigned int* p) {
    unsigned int v;
    asm volatile("ld.acquire.gpu.global.u32 %0, [%1];" : "=r"(v) : "l"(p) : "memory");
    return v;
}

__device__ __forceinline__ void red_release_gpu_add(unsigned int* p, unsigned int v) {
    asm volatile("red.release.gpu.global.add.u32 [%0], %1;" :: "l"(p), "r"(v) : "memory");
}

// ---------------------------------------------------------------------------
// Fused zero + scatter pipeline (DELAY = 2 batch-groups).
//   Block bid:
//     zb = bid >> 9 : zeroes a 16 KB chunk of batch zb's output (zb < 32)
//     sb = zb - 2   : scatters input chunk of batch sb after all 512
//                     zero-blocks of batch sb have published.
//   Producers of batch sb have strictly lower block IDs (>= 1024 earlier);
//   CTAs dispatch in bid order with backfill -> the spin cannot deadlock.
//   BAR.SYNC drains the zero STGs (HW-native on B300); one elected thread
//   publishes with red.release.gpu; consumers poll with ld.acquire.gpu.
//   Scatter REDs then RMW lines that are still L2-resident.
// ---------------------------------------------------------------------------
__global__ void __launch_bounds__(256) fused_unpool_kernel(
    const float4* __restrict__ upd,
    const int4*   __restrict__ mask,
    float*        __restrict__ out)
{
    const int bid = blockIdx.x;
    const int t   = threadIdx.x;
    const int zb  = bid >> 9;              // batch to zero
    const int c   = bid & (BLKS_PER_B - 1);
    const int sb  = zb - DELAY;            // batch to scatter

    const bool do_scatter = (sb >= 0) && (sb < NBATCH);

    // Prefetch scatter inputs (streaming / evict-first: one-shot 128 MB read
    // must not evict the zeroed output window we need resident in L2).
    float4 u = make_float4(0.f, 0.f, 0.f, 0.f);
    int4   m = make_int4(0, 0, 0, 0);
    if (do_scatter) {
        const int vi = (sb << 17) + (c << 8) + t;  // vec4 index within batch
        u = __ldcs(&upd[vi]);
        m = __ldcs(&mask[vi]);
    }

    // ---- zero phase: 16 KB = 1024 float4, 4 per thread, coalesced ----
    if (zb < NBATCH) {
        float4* zp = reinterpret_cast<float4*>(out) +
                     ((size_t)zb << 19) + (c << 10) + t;   // FLAT_OUT/4 = 2^19
        const float4 z = make_float4(0.f, 0.f, 0.f, 0.f);
        zp[0]   = z;
        zp[256] = z;
        zp[512] = z;
        zp[768] = z;

        __syncthreads();               // BAR.SYNC drains pending stores (HW)
        if (t == 0) red_release_gpu_add(&g_ctr[zb], 1u);   // publish
    }

    if (!do_scatter) return;

    // ---- wait until batch sb is fully zeroed (acquire-poll, 1 thread) ----
    if (t == 0) {
        if (ld_acquire_gpu(&g_ctr[sb]) < BLKS_PER_B) {
            do { __nanosleep(32); } while (ld_acquire_gpu(&g_ctr[sb]) < BLKS_PER_B);
        }
    }
    __syncthreads();   // broadcast the acquire to the whole CTA

    // ---- scatter phase: 4 fire-and-forget REDs into the L2-warm window ----
    float* ob = out + ((size_t)sb << 21);                  // FLAT_OUT = 2^21
    atomicAdd(ob + m.x, u.x);
    atomicAdd(ob + m.y, u.y);
    atomicAdd(ob + m.z, u.z);
    atomicAdd(ob + m.w, u.w);
}

extern "C" void kernel_launch(void* const* d_in, const int* in_sizes, int n_in,
                              void* d_out, int out_size)
{
    const float4* upd  = (const float4*)d_in[0];
    const int4*   mask = (const int4*)  d_in[1];
    float*        out  = (float*)d_out;

    init_ctr_kernel<<<1, 32>>>();

    // 32 zero-groups * 512 blocks + DELAY*512 scatter-only tail blocks.
    const int grid = (NBATCH + DELAY) * BLKS_PER_B;   // 17408
    fused_unpool_kernel<<<grid, 256>>>(upd, mask, out);
}

// round 8
// speedup vs baseline: 1.6475x; 1.3128x over previous
#include <cuda_runtime.h>
#include <stdint.h>

// Shapes (fixed):
//   updates: (32, 64, 64, 128) fp32  -> 16,777,216 elems
//   mask:    same shape, int32 in [0, 2,097,152)
//   output:  (32, 128, 128, 128) fp32 -> 67,108,864 elems (256 MB)
#define N_IN        16777216
#define FLAT_OUT    2097152      // per-batch output slots (8 MB)
#define N_OUT       67108864
#define NBATCH      32
#define BLKS_PER_B  256          // blocks per batch group (512 threads each)
#define DELAY       2            // scatter batch = zero batch - DELAY

// Per-batch zero-completion counters (reset every launch by init kernel).
__device__ unsigned int g_ctr[NBATCH];

__global__ void init_ctr_kernel() {
    if (threadIdx.x < NBATCH) g_ctr[threadIdx.x] = 0u;
}

__device__ __forceinline__ unsigned int ld_acquire_gpu(const unsigned int* p) {
    unsigned int v;
    asm volatile("ld.acquire.gpu.global.u32 %0, [%1];" : "=r"(v) : "l"(p) : "memory");
    return v;
}

__device__ __forceinline__ void red_release_gpu_add(unsigned int* p, unsigned int v) {
    asm volatile("red.release.gpu.global.add.u32 [%0], %1;" :: "l"(p), "r"(v) : "memory");
}

// ---------------------------------------------------------------------------
// Fused zero + scatter pipeline, 512-thread blocks (half the blocks of R6
// -> half the barriers / publishes / acquire-polls / wave transitions).
//   Block bid:
//     zb = bid >> 8 : zeroes a 32 KB chunk of batch zb's output (zb < 32)
//     sb = zb - 2   : scatters a 2048-element input chunk of batch sb after
//                     all 256 zero-blocks of batch sb have published.
//   Producers of batch sb have strictly lower block IDs (>= 512 earlier);
//   CTAs dispatch in bid order with backfill -> the spin cannot deadlock.
//   BAR.SYNC drains the zero STGs (HW-native on B300); one elected thread
//   publishes with red.release.gpu; consumers poll with ld.acquire.gpu.
//   Scatter REDs then RMW lines that are still L2-resident.
// ---------------------------------------------------------------------------
__global__ void __launch_bounds__(512) fused_unpool_kernel(
    const float4* __restrict__ upd,
    const int4*   __restrict__ mask,
    float*        __restrict__ out)
{
    const int bid = blockIdx.x;
    const int t   = threadIdx.x;                // 0..511
    const int zb  = bid >> 8;                   // batch to zero
    const int c   = bid & (BLKS_PER_B - 1);     // chunk within group
    const int sb  = zb - DELAY;                 // batch to scatter

    const bool do_scatter = (sb >= 0) && (sb < NBATCH);

    // Prefetch scatter inputs (streaming / evict-first: the one-shot 128 MB
    // input read must not evict the zeroed output window from L2).
    float4 u = make_float4(0.f, 0.f, 0.f, 0.f);
    int4   m = make_int4(0, 0, 0, 0);
    if (do_scatter) {
        const int vi = (sb << 17) + (c << 9) + t;   // vec4 index within batch
        u = __ldcs(&upd[vi]);
        m = __ldcs(&mask[vi]);
    }

    // ---- zero phase: 32 KB = 2048 float4, 4 per thread, coalesced ----
    if (zb < NBATCH) {
        float4* zp = reinterpret_cast<float4*>(out) +
                     ((size_t)zb << 19) + (c << 11) + t;    // FLAT_OUT/4 = 2^19
        const float4 z = make_float4(0.f, 0.f, 0.f, 0.f);
        zp[0]    = z;
        zp[512]  = z;
        zp[1024] = z;
        zp[1536] = z;

        __syncthreads();               // BAR.SYNC drains pending stores (HW)
        if (t == 0) red_release_gpu_add(&g_ctr[zb], 1u);    // publish
    }

    if (!do_scatter) return;

    // ---- wait until batch sb is fully zeroed (acquire-poll, 1 thread) ----
    if (t == 0) {
        if (ld_acquire_gpu(&g_ctr[sb]) < BLKS_PER_B) {
            do { __nanosleep(32); } while (ld_acquire_gpu(&g_ctr[sb]) < BLKS_PER_B);
        }
    }
    __syncthreads();   // broadcast the acquire to the whole CTA

    // ---- scatter phase: 4 fire-and-forget REDs into the L2-warm window ----
    float* ob = out + ((size_t)sb << 21);                   // FLAT_OUT = 2^21
    atomicAdd(ob + m.x, u.x);
    atomicAdd(ob + m.y, u.y);
    atomicAdd(ob + m.z, u.z);
    atomicAdd(ob + m.w, u.w);
}

extern "C" void kernel_launch(void* const* d_in, const int* in_sizes, int n_in,
                              void* d_out, int out_size)
{
    const float4* upd  = (const float4*)d_in[0];
    const int4*   mask = (const int4*)  d_in[1];
    float*        out  = (float*)d_out;

    init_ctr_kernel<<<1, 32>>>();

    // 32 zero-groups * 256 blocks + DELAY*256 scatter-only tail blocks.
    const int grid = (NBATCH + DELAY) * BLKS_PER_B;   // 8704
    fused_unpool_kernel<<<grid, 512>>>(upd, mask, out);
}

// round 9
// speedup vs baseline: 1.7596x; 1.0680x over previous
#include <cuda_runtime.h>
#include <stdint.h>

// Shapes (fixed):
//   updates: (32, 64, 64, 128) fp32  -> 16,777,216 elems
//   mask:    same shape, int32 in [0, 2,097,152)
//   output:  (32, 128, 128, 128) fp32 -> 67,108,864 elems (256 MB)
#define N_IN        16777216
#define FLAT_OUT    2097152      // per-batch output slots (8 MB)
#define N_OUT       67108864
#define NBATCH      32
#define BLKS_PER_B  128          // blocks per batch group (1024 threads each)
#define DELAY       2            // scatter batch = zero batch - DELAY

// Per-batch zero-completion counters (reset every launch by init kernel).
__device__ unsigned int g_ctr[NBATCH];

__global__ void init_ctr_kernel() {
    if (threadIdx.x < NBATCH) g_ctr[threadIdx.x] = 0u;
}

__device__ __forceinline__ unsigned int ld_acquire_gpu(const unsigned int* p) {
    unsigned int v;
    asm volatile("ld.acquire.gpu.global.u32 %0, [%1];" : "=r"(v) : "l"(p) : "memory");
    return v;
}

__device__ __forceinline__ void red_release_gpu_add(unsigned int* p, unsigned int v) {
    asm volatile("red.release.gpu.global.add.u32 [%0], %1;" :: "l"(p), "r"(v) : "memory");
}

// ---------------------------------------------------------------------------
// Fused zero + scatter pipeline, 1024-thread blocks (half the blocks of R7
// -> half the barriers / publishes / acquire-poll rounds again; per-thread
// instruction shape unchanged so regs/occupancy hold).
//   Block bid:
//     zb = bid >> 7 : zeroes a 64 KB chunk of batch zb's output (zb < 32)
//     sb = zb - 2   : scatters a 4096-element input chunk of batch sb after
//                     all 128 zero-blocks of batch sb have published.
//   Producers of batch sb have strictly lower block IDs (>= 256 earlier);
//   CTAs dispatch in bid order with backfill -> the spin cannot deadlock.
//   BAR.SYNC drains the zero STGs (HW-native on B300); one elected thread
//   publishes with red.release.gpu; consumers poll with ld.acquire.gpu.
//   Scatter REDs then RMW lines that are still L2-resident.
// ---------------------------------------------------------------------------
__global__ void __launch_bounds__(1024) fused_unpool_kernel(
    const float4* __restrict__ upd,
    const int4*   __restrict__ mask,
    float*        __restrict__ out)
{
    const int bid = blockIdx.x;
    const int t   = threadIdx.x;                // 0..1023
    const int zb  = bid >> 7;                   // batch to zero
    const int c   = bid & (BLKS_PER_B - 1);     // chunk within group
    const int sb  = zb - DELAY;                 // batch to scatter

    const bool do_scatter = (sb >= 0) && (sb < NBATCH);

    // Prefetch scatter inputs (streaming / evict-first: the one-shot 128 MB
    // input read must not evict the zeroed output window from L2).
    float4 u = make_float4(0.f, 0.f, 0.f, 0.f);
    int4   m = make_int4(0, 0, 0, 0);
    if (do_scatter) {
        const int vi = (sb << 17) + (c << 10) + t;  // vec4 index within batch
        u = __ldcs(&upd[vi]);
        m = __ldcs(&mask[vi]);
    }

    // ---- zero phase: 64 KB = 4096 float4, 4 per thread, coalesced ----
    if (zb < NBATCH) {
        float4* zp = reinterpret_cast<float4*>(out) +
                     ((size_t)zb << 19) + (c << 12) + t;    // FLAT_OUT/4 = 2^19
        const float4 z = make_float4(0.f, 0.f, 0.f, 0.f);
        zp[0]    = z;
        zp[1024] = z;
        zp[2048] = z;
        zp[3072] = z;

        __syncthreads();               // BAR.SYNC drains pending stores (HW)
        if (t == 0) red_release_gpu_add(&g_ctr[zb], 1u);    // publish
    }

    if (!do_scatter) return;

    // ---- wait until batch sb is fully zeroed (acquire-poll, 1 thread) ----
    if (t == 0) {
        if (ld_acquire_gpu(&g_ctr[sb]) < BLKS_PER_B) {
            do { __nanosleep(32); } while (ld_acquire_gpu(&g_ctr[sb]) < BLKS_PER_B);
        }
    }
    __syncthreads();   // broadcast the acquire to the whole CTA

    // ---- scatter phase: 4 fire-and-forget REDs into the L2-warm window ----
    float* ob = out + ((size_t)sb << 21);                   // FLAT_OUT = 2^21
    atomicAdd(ob + m.x, u.x);
    atomicAdd(ob + m.y, u.y);
    atomicAdd(ob + m.z, u.z);
    atomicAdd(ob + m.w, u.w);
}

extern "C" void kernel_launch(void* const* d_in, const int* in_sizes, int n_in,
                              void* d_out, int out_size)
{
    const float4* upd  = (const float4*)d_in[0];
    const int4*   mask = (const int4*)  d_in[1];
    float*        out  = (float*)d_out;

    init_ctr_kernel<<<1, 32>>>();

    // 32 zero-groups * 128 blocks + DELAY*128 scatter-only tail blocks.
    const int grid = (NBATCH + DELAY) * BLKS_PER_B;   // 4352
    fused_unpool_kernel<<<grid, 1024>>>(upd, mask, out);
}